// round 3
// baseline (speedup 1.0000x reference)
#include <cuda_runtime.h>

#define B_    64
#define S_    512
#define DIN_  512
#define DH_   1024
#define NCTA_RNN 128
#define RNN_SMEM (65536 + 18432)   // h pairs (8*1024*8B) + padded reduction buffer

__device__ unsigned g_bar;

// ---------------- packed f32x2 helpers (FFMA2 on sm_103a) ----------------
static __device__ __forceinline__ unsigned long long pack2(float x, float y) {
    unsigned long long r;
    asm("mov.b64 %0, {%1, %2};" : "=l"(r) : "f"(x), "f"(y));
    return r;
}
static __device__ __forceinline__ void unpack2(unsigned long long v, float &x, float &y) {
    asm("mov.b64 {%0, %1}, %2;" : "=f"(x), "=f"(y) : "l"(v));
}
static __device__ __forceinline__ unsigned long long ffma2(unsigned long long a,
                                                           unsigned long long b,
                                                           unsigned long long c) {
    unsigned long long d;
    asm("fma.rn.f32x2 %0, %1, %2, %3;" : "=l"(d) : "l"(a), "l"(b), "l"(c));
    return d;
}

// ---------------- Kernel 1: xproj = x @ Wx + b, written into outs region ----------------
// M = B*S = 32768, N = DH = 1024, K = DIN = 512.
// Tile 128x64x16, 256 threads, thread tile 8(m) x 4(n), fp32x2 packed along m.
__global__ __launch_bounds__(256) void xproj_kernel(
    const float* __restrict__ X,
    const float* __restrict__ W,      // full (1536,1024); Wx = rows [0,512)
    const float* __restrict__ bias,
    float* __restrict__ C)            // (32768, 1024) = outs region
{
    __shared__ __align__(16) float As[16][132];   // [k][m], padded
    __shared__ __align__(16) float Bs[16][64];    // [k][n]

    const int tid = threadIdx.x;
    const int m0 = blockIdx.y * 128;
    const int n0 = blockIdx.x * 64;
    const int tx = tid & 15;          // n-dim
    const int ty = tid >> 4;          // m-dim
    const int ar = tid >> 2;          // 0..63
    const int ac = (tid & 3) << 2;    // 0,4,8,12
    const int br = tid >> 4;          // 0..15
    const int bc = (tid & 15) << 2;   // 0..60

    unsigned long long acc[4][4];
#pragma unroll
    for (int i = 0; i < 4; ++i)
#pragma unroll
        for (int jj = 0; jj < 4; ++jj) acc[i][jj] = 0ull;

    for (int kt = 0; kt < DIN_; kt += 16) {
        float4 a0 = *(const float4*)(X + (size_t)(m0 + ar) * DIN_ + kt + ac);
        float4 a1 = *(const float4*)(X + (size_t)(m0 + ar + 64) * DIN_ + kt + ac);
        float4 bv = *(const float4*)(W + (size_t)(kt + br) * DH_ + n0 + bc);
        As[ac + 0][ar] = a0.x; As[ac + 1][ar] = a0.y;
        As[ac + 2][ar] = a0.z; As[ac + 3][ar] = a0.w;
        As[ac + 0][ar + 64] = a1.x; As[ac + 1][ar + 64] = a1.y;
        As[ac + 2][ar + 64] = a1.z; As[ac + 3][ar + 64] = a1.w;
        *(float4*)&Bs[br][bc] = bv;
        __syncthreads();

#pragma unroll
        for (int k = 0; k < 16; ++k) {
            const unsigned long long* ap =
                (const unsigned long long*)&As[k][ty << 3];
            ulonglong2 av0 = *(const ulonglong2*)(ap);
            ulonglong2 av1 = *(const ulonglong2*)(ap + 2);
            unsigned long long a2[4] = { av0.x, av0.y, av1.x, av1.y };
            float4 bq = *(const float4*)&Bs[k][tx << 2];
            unsigned long long b2[4] = { pack2(bq.x, bq.x), pack2(bq.y, bq.y),
                                         pack2(bq.z, bq.z), pack2(bq.w, bq.w) };
#pragma unroll
            for (int i = 0; i < 4; ++i)
#pragma unroll
                for (int jj = 0; jj < 4; ++jj)
                    acc[i][jj] = ffma2(a2[i], b2[jj], acc[i][jj]);
        }
        __syncthreads();
    }

    float4 bias4 = *(const float4*)(bias + n0 + (tx << 2));
#pragma unroll
    for (int i = 0; i < 4; ++i) {
        float l0, h0, l1, h1, l2, h2, l3, h3;
        unpack2(acc[i][0], l0, h0);
        unpack2(acc[i][1], l1, h1);
        unpack2(acc[i][2], l2, h2);
        unpack2(acc[i][3], l3, h3);
        int m = m0 + (ty << 3) + (i << 1);
        float4 v0 = make_float4(l0 + bias4.x, l1 + bias4.y, l2 + bias4.z, l3 + bias4.w);
        float4 v1 = make_float4(h0 + bias4.x, h1 + bias4.y, h2 + bias4.z, h3 + bias4.w);
        *(float4*)(C + (size_t)m * DH_ + n0 + (tx << 2)) = v0;
        *(float4*)(C + (size_t)(m + 1) * DH_ + n0 + (tx << 2)) = v1;
    }
}

// ---------------- barrier reset (run before recurrence every launch) ----------------
__global__ void reset_kernel() { g_bar = 0u; }

// ---------------- Kernel 2: persistent recurrence ----------------
// 128 CTAs = 32 col-groups (32 cols each) x 4 batch-groups (16 batches = 8 pairs each).
// Per step: y[b][j] = sum_k h[b][k]*Wh[k][j]; h = tanh(xp + y), in place in `out`.
// Grid barrier between steps via atomic counter.
__global__ __launch_bounds__(256) void rnn_kernel(
    const float* __restrict__ h0,
    const float* __restrict__ W,      // Wh = rows [512, 1536)
    float* __restrict__ out,          // (B,S,DH): xp in, h out (in place)
    float* __restrict__ hlast)        // (B, DH)
{
    extern __shared__ unsigned char sraw[];
    float2* hs = (float2*)sraw;                     // [8 pairs][1024 k]
    float2* red = (float2*)(sraw + 65536);          // [(bp*32+js)*9 + ks], padded

    const int tid = threadIdx.x;
    const int cg = blockIdx.x & 31;       // col group 0..31
    const int bg = blockIdx.x >> 5;       // batch group 0..3
    const int js = tid & 31;              // 0..31 (column within group)
    const int ks = tid >> 5;              // 0..7  (k split)
    const int j = (cg << 5) + js;
    const float* Wcol = W + (size_t)DIN_ * DH_ + j;   // Wh[0][j]
    const unsigned long long* hsu = (const unsigned long long*)hs;
    const int k4 = tid << 2;              // 0..1020

    for (int t = 0; t < S_; ++t) {
        // ---- stage h_prev (16 batches) into smem as batch-pairs ----
        {
            const float* base;
            size_t rstride;
            if (t == 0) { base = h0 + (size_t)(bg << 4) * DH_; rstride = DH_; }
            else {
                base = out + ((size_t)(bg << 4) * S_ + (t - 1)) * DH_;
                rstride = (size_t)S_ * DH_;
            }
#pragma unroll
            for (int bp = 0; bp < 8; ++bp) {
                const float* r0 = base + (size_t)(2 * bp) * rstride + k4;
                const float* r1 = r0 + rstride;
                float4 a = *(const float4*)r0;
                float4 b = *(const float4*)r1;
                float2* d = hs + bp * 1024 + k4;
                d[0] = make_float2(a.x, b.x);
                d[1] = make_float2(a.y, b.y);
                d[2] = make_float2(a.z, b.z);
                d[3] = make_float2(a.w, b.w);
            }
        }
        __syncthreads();

        // ---- packed GEMV: 8 batch-pair accumulators, K-slice of 128 ----
        unsigned long long acc[8];
#pragma unroll
        for (int bp = 0; bp < 8; ++bp) acc[bp] = 0ull;

        const float* wp = Wcol + (size_t)(ks << 7) * DH_;
        const int kbase = ks << 7;
#pragma unroll 4
        for (int kk = 0; kk < 128; kk += 2) {
            float w0 = wp[(size_t)kk * DH_];
            float w1 = wp[(size_t)(kk + 1) * DH_];
            unsigned long long w20 = pack2(w0, w0);
            unsigned long long w21 = pack2(w1, w1);
#pragma unroll
            for (int bp = 0; bp < 8; ++bp) {
                ulonglong2 h2 = *(const ulonglong2*)(hsu + (size_t)bp * 1024 + kbase + kk);
                acc[bp] = ffma2(h2.x, w20, acc[bp]);
                acc[bp] = ffma2(h2.y, w21, acc[bp]);
            }
        }

        // ---- K-split reduction through smem ----
#pragma unroll
        for (int bp = 0; bp < 8; ++bp) {
            float x, y;
            unpack2(acc[bp], x, y);
            red[((bp << 5) + js) * 9 + ks] = make_float2(x, y);
        }
        __syncthreads();

        {
            const int bp2 = tid >> 5;     // 0..7
            const int js2 = tid & 31;
            const float2* rp = red + ((bp2 << 5) + js2) * 9;
            float sx = 0.f, sy = 0.f;
#pragma unroll
            for (int q = 0; q < 8; ++q) { sx += rp[q].x; sy += rp[q].y; }
            const int jo = (cg << 5) + js2;
            const int b0 = (bg << 4) + (bp2 << 1);
            const size_t i0 = ((size_t)b0 * S_ + t) * DH_ + jo;
            const size_t i1 = i0 + (size_t)S_ * DH_;
            float hv0 = tanhf(out[i0] + sx);
            float hv1 = tanhf(out[i1] + sy);
            out[i0] = hv0;
            out[i1] = hv1;
            if (t == S_ - 1) {
                hlast[(size_t)b0 * DH_ + jo] = hv0;
                hlast[(size_t)(b0 + 1) * DH_ + jo] = hv1;
            }
        }

        // ---- grid barrier ----
        __threadfence();
        __syncthreads();
        if (tid == 0) {
            const unsigned target = (unsigned)NCTA_RNN * (unsigned)(t + 1);
            atomicAdd(&g_bar, 1u);
            while (*(volatile unsigned*)&g_bar < target) { }
            __threadfence();
        }
        __syncthreads();
    }
}

// ---------------- launch ----------------
extern "C" void kernel_launch(void* const* d_in, const int* in_sizes, int n_in,
                              void* d_out, int out_size) {
    (void)in_sizes; (void)n_in; (void)out_size;
    const float* x  = (const float*)d_in[0];
    const float* h0 = (const float*)d_in[1];
    const float* W  = (const float*)d_in[2];
    const float* b  = (const float*)d_in[3];
    float* out = (float*)d_out;                       // (B,S,DH) outs
    float* hlast = out + (size_t)B_ * S_ * DH_;       // (B,DH) h_last

    cudaFuncSetAttribute(rnn_kernel, cudaFuncAttributeMaxDynamicSharedMemorySize, RNN_SMEM);

    dim3 g1(DH_ / 64, (B_ * S_) / 128);
    xproj_kernel<<<g1, 256>>>(x, W, b, out);
    reset_kernel<<<1, 1>>>();
    rnn_kernel<<<NCTA_RNN, 256, RNN_SMEM>>>(h0, W, out, hlast);
}

// round 4
// speedup vs baseline: 1.5079x; 1.5079x over previous
#include <cuda_runtime.h>

#define B_    64
#define S_    512
#define DIN_  512
#define DH_   1024
#define NCTA_RNN 128
// smem: Wh slice (1024*32*4B=128KB) + h pairs (8*1024*8B=64KB) + reduction (18KB)
#define RNN_SMEM (131072 + 65536 + 18432)

__device__ unsigned g_bar;
__device__ float g_hbuf[2][B_ * DH_];   // compact ping-pong h buffer (L2-hot)

// ---------------- packed f32x2 helpers (FFMA2 on sm_103a) ----------------
static __device__ __forceinline__ unsigned long long pack2(float x, float y) {
    unsigned long long r;
    asm("mov.b64 %0, {%1, %2};" : "=l"(r) : "f"(x), "f"(y));
    return r;
}
static __device__ __forceinline__ void unpack2(unsigned long long v, float &x, float &y) {
    asm("mov.b64 {%0, %1}, %2;" : "=f"(x), "=f"(y) : "l"(v));
}
static __device__ __forceinline__ unsigned long long ffma2(unsigned long long a,
                                                           unsigned long long b,
                                                           unsigned long long c) {
    unsigned long long d;
    asm("fma.rn.f32x2 %0, %1, %2, %3;" : "=l"(d) : "l"(a), "l"(b), "l"(c));
    return d;
}

// ---------------- Kernel 1: xproj = x @ Wx + b, written into outs region ----------------
__global__ __launch_bounds__(256) void xproj_kernel(
    const float* __restrict__ X,
    const float* __restrict__ W,      // full (1536,1024); Wx = rows [0,512)
    const float* __restrict__ bias,
    float* __restrict__ C)            // (32768, 1024) = outs region
{
    __shared__ __align__(16) float As[16][132];   // [k][m], padded
    __shared__ __align__(16) float Bs[16][64];    // [k][n]

    const int tid = threadIdx.x;
    const int m0 = blockIdx.y * 128;
    const int n0 = blockIdx.x * 64;
    const int tx = tid & 15;          // n-dim
    const int ty = tid >> 4;          // m-dim
    const int ar = tid >> 2;          // 0..63
    const int ac = (tid & 3) << 2;    // 0,4,8,12
    const int br = tid >> 4;          // 0..15
    const int bc = (tid & 15) << 2;   // 0..60

    unsigned long long acc[4][4];
#pragma unroll
    for (int i = 0; i < 4; ++i)
#pragma unroll
        for (int jj = 0; jj < 4; ++jj) acc[i][jj] = 0ull;

    for (int kt = 0; kt < DIN_; kt += 16) {
        float4 a0 = *(const float4*)(X + (size_t)(m0 + ar) * DIN_ + kt + ac);
        float4 a1 = *(const float4*)(X + (size_t)(m0 + ar + 64) * DIN_ + kt + ac);
        float4 bv = *(const float4*)(W + (size_t)(kt + br) * DH_ + n0 + bc);
        As[ac + 0][ar] = a0.x; As[ac + 1][ar] = a0.y;
        As[ac + 2][ar] = a0.z; As[ac + 3][ar] = a0.w;
        As[ac + 0][ar + 64] = a1.x; As[ac + 1][ar + 64] = a1.y;
        As[ac + 2][ar + 64] = a1.z; As[ac + 3][ar + 64] = a1.w;
        *(float4*)&Bs[br][bc] = bv;
        __syncthreads();

#pragma unroll
        for (int k = 0; k < 16; ++k) {
            const unsigned long long* ap =
                (const unsigned long long*)&As[k][ty << 3];
            ulonglong2 av0 = *(const ulonglong2*)(ap);
            ulonglong2 av1 = *(const ulonglong2*)(ap + 2);
            unsigned long long a2[4] = { av0.x, av0.y, av1.x, av1.y };
            float4 bq = *(const float4*)&Bs[k][tx << 2];
            unsigned long long b2[4] = { pack2(bq.x, bq.x), pack2(bq.y, bq.y),
                                         pack2(bq.z, bq.z), pack2(bq.w, bq.w) };
#pragma unroll
            for (int i = 0; i < 4; ++i)
#pragma unroll
                for (int jj = 0; jj < 4; ++jj)
                    acc[i][jj] = ffma2(a2[i], b2[jj], acc[i][jj]);
        }
        __syncthreads();
    }

    float4 bias4 = *(const float4*)(bias + n0 + (tx << 2));
#pragma unroll
    for (int i = 0; i < 4; ++i) {
        float l0, h0, l1, h1, l2, h2, l3, h3;
        unpack2(acc[i][0], l0, h0);
        unpack2(acc[i][1], l1, h1);
        unpack2(acc[i][2], l2, h2);
        unpack2(acc[i][3], l3, h3);
        int m = m0 + (ty << 3) + (i << 1);
        float4 v0 = make_float4(l0 + bias4.x, l1 + bias4.y, l2 + bias4.z, l3 + bias4.w);
        float4 v1 = make_float4(h0 + bias4.x, h1 + bias4.y, h2 + bias4.z, h3 + bias4.w);
        *(float4*)(C + (size_t)m * DH_ + n0 + (tx << 2)) = v0;
        *(float4*)(C + (size_t)(m + 1) * DH_ + n0 + (tx << 2)) = v1;
    }
}

// ---------------- barrier reset (run before recurrence every launch) ----------------
__global__ void reset_kernel() { g_bar = 0u; }

// ---------------- Kernel 2: persistent recurrence ----------------
// 128 CTAs = 32 col-groups (32 cols) x 4 batch-groups (16 batches = 8 pairs).
// Wh column-slice cached in SMEM once. h all-gathered per step via a compact
// ping-pong global buffer. Grid barrier = single-thread release/acquire.
__global__ __launch_bounds__(256) void rnn_kernel(
    const float* __restrict__ h0,
    const float* __restrict__ W,      // Wh = rows [512, 1536)
    float* __restrict__ out,          // (B,S,DH): xp in, h out (in place)
    float* __restrict__ hlast)        // (B, DH)
{
    extern __shared__ unsigned char sraw[];
    float*  ws  = (float*)sraw;                            // [1024][32]  Wh slice
    float2* hs  = (float2*)(sraw + 131072);                // [8 pairs][1024]
    float2* red = (float2*)(sraw + 131072 + 65536);        // [(bp*32+js)*9 + ks]

    const int tid = threadIdx.x;
    const int cg = blockIdx.x & 31;       // col group 0..31
    const int bg = blockIdx.x >> 5;       // batch group 0..3
    const int js = tid & 31;              // column within group
    const int ks = tid >> 5;              // k-split 0..7
    const unsigned long long* hsu = (const unsigned long long*)hs;
    const int k4 = tid << 2;

    // epilogue mapping (fixed per thread)
    const int bp2 = tid >> 5;
    const int js2 = tid & 31;
    const int jo = (cg << 5) + js2;
    const int b0 = (bg << 4) + (bp2 << 1);

    // ---- one-time: stage Wh slice (1024 x 32) into smem ----
    {
        const float* wsrc = W + (size_t)DIN_ * DH_ + (cg << 5);
        for (int idx = tid; idx < (1024 * 32) / 4; idx += 256) {
            int r = idx >> 3;
            int c = (idx & 7) << 2;
            float4 v = *(const float4*)(wsrc + (size_t)r * DH_ + c);
            *(float4*)(ws + r * 32 + c) = v;
        }
    }
    __syncthreads();

    for (int t = 0; t < S_; ++t) {
        // ---- prefetch xp for this step (overlaps with GEMV; no writer until us) ----
        const size_t i0 = ((size_t)b0 * S_ + t) * DH_ + jo;
        const size_t i1 = i0 + (size_t)S_ * DH_;
        float xp0 = out[i0];
        float xp1 = out[i1];

        // ---- stage h_prev (16 batches) into smem as batch-pairs ----
        {
            const float* base = (t == 0)
                ? (h0 + (size_t)(bg << 4) * DH_)
                : (g_hbuf[(t - 1) & 1] + (size_t)(bg << 4) * DH_);
#pragma unroll
            for (int bp = 0; bp < 8; ++bp) {
                const float* r0 = base + (size_t)(bp << 1) * DH_ + k4;
                float4 a = *(const float4*)r0;
                float4 b = *(const float4*)(r0 + DH_);
                float2* d = hs + bp * 1024 + k4;
                d[0] = make_float2(a.x, b.x);
                d[1] = make_float2(a.y, b.y);
                d[2] = make_float2(a.z, b.z);
                d[3] = make_float2(a.w, b.w);
            }
        }
        __syncthreads();

        // ---- packed GEMV: all operands in smem ----
        unsigned long long acc[8];
#pragma unroll
        for (int bp = 0; bp < 8; ++bp) acc[bp] = 0ull;

        const int kbase = ks << 7;
        const float* wp = ws + kbase * 32 + js;
        const unsigned long long* hp = hsu + kbase;
#pragma unroll 4
        for (int kk = 0; kk < 128; kk += 2) {
            float w0 = wp[kk * 32];
            float w1 = wp[kk * 32 + 32];
            unsigned long long w20 = pack2(w0, w0);
            unsigned long long w21 = pack2(w1, w1);
#pragma unroll
            for (int bp = 0; bp < 8; ++bp) {
                ulonglong2 h2 = *(const ulonglong2*)(hp + bp * 1024 + kk);
                acc[bp] = ffma2(h2.x, w20, acc[bp]);
                acc[bp] = ffma2(h2.y, w21, acc[bp]);
            }
        }

        // ---- K-split reduction through smem ----
#pragma unroll
        for (int bp = 0; bp < 8; ++bp) {
            float x, y;
            unpack2(acc[bp], x, y);
            red[((bp << 5) + js) * 9 + ks] = make_float2(x, y);
        }
        __syncthreads();

        {
            const float2* rp = red + ((bp2 << 5) + js2) * 9;
            float sx = 0.f, sy = 0.f;
#pragma unroll
            for (int q = 0; q < 8; ++q) { sx += rp[q].x; sy += rp[q].y; }
            float hv0 = tanhf(xp0 + sx);
            float hv1 = tanhf(xp1 + sy);
            out[i0] = hv0;
            out[i1] = hv1;
            float* hb = g_hbuf[t & 1];
            hb[(size_t)b0 * DH_ + jo] = hv0;
            hb[(size_t)(b0 + 1) * DH_ + jo] = hv1;
            if (t == S_ - 1) {
                hlast[(size_t)b0 * DH_ + jo] = hv0;
                hlast[(size_t)(b0 + 1) * DH_ + jo] = hv1;
            }
        }

        // ---- grid barrier: cumulative release/acquire, single thread ----
        __syncthreads();
        if (tid == 0) {
            unsigned long long addr = (unsigned long long)&g_bar;
            asm volatile("red.release.gpu.add.u32 [%0], 1;" :: "l"(addr) : "memory");
            const unsigned target = (unsigned)NCTA_RNN * (unsigned)(t + 1);
            unsigned v;
            do {
                asm volatile("ld.acquire.gpu.u32 %0, [%1];" : "=r"(v) : "l"(addr) : "memory");
            } while (v < target);
        }
        __syncthreads();
    }
}

// ---------------- launch ----------------
extern "C" void kernel_launch(void* const* d_in, const int* in_sizes, int n_in,
                              void* d_out, int out_size) {
    (void)in_sizes; (void)n_in; (void)out_size;
    const float* x  = (const float*)d_in[0];
    const float* h0 = (const float*)d_in[1];
    const float* W  = (const float*)d_in[2];
    const float* b  = (const float*)d_in[3];
    float* out = (float*)d_out;                       // (B,S,DH) outs
    float* hlast = out + (size_t)B_ * S_ * DH_;       // (B,DH) h_last

    cudaFuncSetAttribute(rnn_kernel, cudaFuncAttributeMaxDynamicSharedMemorySize, RNN_SMEM);

    dim3 g1(DH_ / 64, (B_ * S_) / 128);
    xproj_kernel<<<g1, 256>>>(x, W, b, out);
    reset_kernel<<<1, 1>>>();
    rnn_kernel<<<NCTA_RNN, 256, RNN_SMEM>>>(h0, W, out, hlast);
}

// round 5
// speedup vs baseline: 1.5725x; 1.0429x over previous
#include <cuda_runtime.h>

#define B_    64
#define S_    512
#define DIN_  512
#define DH_   1024
#define NCTA_RNN 128
#define RNN_THREADS 512
// smem: Wh slice (1024*32*4B=128KB) + h pairs (8*1024*8B=64KB) + reduction (16*256*8B=32KB)
#define RNN_SMEM (131072 + 65536 + 32768)

__device__ unsigned g_bar;
__device__ float g_hbuf[2][B_ * DH_];   // compact ping-pong h buffer (L2-hot)

// ---------------- packed f32x2 helpers (FFMA2 on sm_103a) ----------------
static __device__ __forceinline__ unsigned long long pack2(float x, float y) {
    unsigned long long r;
    asm("mov.b64 %0, {%1, %2};" : "=l"(r) : "f"(x), "f"(y));
    return r;
}
static __device__ __forceinline__ void unpack2(unsigned long long v, float &x, float &y) {
    asm("mov.b64 {%0, %1}, %2;" : "=f"(x), "=f"(y) : "l"(v));
}
static __device__ __forceinline__ unsigned long long ffma2(unsigned long long a,
                                                           unsigned long long b,
                                                           unsigned long long c) {
    unsigned long long d;
    asm("fma.rn.f32x2 %0, %1, %2, %3;" : "=l"(d) : "l"(a), "l"(b), "l"(c));
    return d;
}

// ---------------- Kernel 1: xproj = x @ Wx + b, written into outs region ----------------
__global__ __launch_bounds__(256) void xproj_kernel(
    const float* __restrict__ X,
    const float* __restrict__ W,      // full (1536,1024); Wx = rows [0,512)
    const float* __restrict__ bias,
    float* __restrict__ C)            // (32768, 1024) = outs region
{
    __shared__ __align__(16) float As[16][132];   // [k][m], padded
    __shared__ __align__(16) float Bs[16][64];    // [k][n]

    const int tid = threadIdx.x;
    const int m0 = blockIdx.y * 128;
    const int n0 = blockIdx.x * 64;
    const int tx = tid & 15;          // n-dim
    const int ty = tid >> 4;          // m-dim
    const int ar = tid >> 2;          // 0..63
    const int ac = (tid & 3) << 2;    // 0,4,8,12
    const int br = tid >> 4;          // 0..15
    const int bc = (tid & 15) << 2;   // 0..60

    unsigned long long acc[4][4];
#pragma unroll
    for (int i = 0; i < 4; ++i)
#pragma unroll
        for (int jj = 0; jj < 4; ++jj) acc[i][jj] = 0ull;

    for (int kt = 0; kt < DIN_; kt += 16) {
        float4 a0 = *(const float4*)(X + (size_t)(m0 + ar) * DIN_ + kt + ac);
        float4 a1 = *(const float4*)(X + (size_t)(m0 + ar + 64) * DIN_ + kt + ac);
        float4 bv = *(const float4*)(W + (size_t)(kt + br) * DH_ + n0 + bc);
        As[ac + 0][ar] = a0.x; As[ac + 1][ar] = a0.y;
        As[ac + 2][ar] = a0.z; As[ac + 3][ar] = a0.w;
        As[ac + 0][ar + 64] = a1.x; As[ac + 1][ar + 64] = a1.y;
        As[ac + 2][ar + 64] = a1.z; As[ac + 3][ar + 64] = a1.w;
        *(float4*)&Bs[br][bc] = bv;
        __syncthreads();

#pragma unroll
        for (int k = 0; k < 16; ++k) {
            const unsigned long long* ap =
                (const unsigned long long*)&As[k][ty << 3];
            ulonglong2 av0 = *(const ulonglong2*)(ap);
            ulonglong2 av1 = *(const ulonglong2*)(ap + 2);
            unsigned long long a2[4] = { av0.x, av0.y, av1.x, av1.y };
            float4 bq = *(const float4*)&Bs[k][tx << 2];
            unsigned long long b2[4] = { pack2(bq.x, bq.x), pack2(bq.y, bq.y),
                                         pack2(bq.z, bq.z), pack2(bq.w, bq.w) };
#pragma unroll
            for (int i = 0; i < 4; ++i)
#pragma unroll
                for (int jj = 0; jj < 4; ++jj)
                    acc[i][jj] = ffma2(a2[i], b2[jj], acc[i][jj]);
        }
        __syncthreads();
    }

    float4 bias4 = *(const float4*)(bias + n0 + (tx << 2));
#pragma unroll
    for (int i = 0; i < 4; ++i) {
        float l0, h0, l1, h1, l2, h2, l3, h3;
        unpack2(acc[i][0], l0, h0);
        unpack2(acc[i][1], l1, h1);
        unpack2(acc[i][2], l2, h2);
        unpack2(acc[i][3], l3, h3);
        int m = m0 + (ty << 3) + (i << 1);
        float4 v0 = make_float4(l0 + bias4.x, l1 + bias4.y, l2 + bias4.z, l3 + bias4.w);
        float4 v1 = make_float4(h0 + bias4.x, h1 + bias4.y, h2 + bias4.z, h3 + bias4.w);
        *(float4*)(C + (size_t)m * DH_ + n0 + (tx << 2)) = v0;
        *(float4*)(C + (size_t)(m + 1) * DH_ + n0 + (tx << 2)) = v1;
    }
}

// ---------------- barrier reset (run before recurrence every launch) ----------------
__global__ void reset_kernel() { g_bar = 0u; }

// ---------------- Kernel 2: persistent recurrence, 512 threads ----------------
// 128 CTAs = 32 col-groups (32 cols) x 4 batch-groups (16 batches = 8 pairs).
// 16 warps: warp = one 64-k slice, lanes = 32 columns.
__global__ __launch_bounds__(RNN_THREADS, 1) void rnn_kernel(
    const float* __restrict__ h0,
    const float* __restrict__ W,      // Wh = rows [512, 1536)
    float* __restrict__ out,          // (B,S,DH): xp in, h out (in place)
    float* __restrict__ hlast)        // (B, DH)
{
    extern __shared__ unsigned char sraw[];
    float*  ws   = (float*)sraw;                           // [1024][32]  Wh slice
    float2* hs   = (float2*)(sraw + 131072);               // [8 pairs][1024]
    unsigned long long* redu =
        (unsigned long long*)(sraw + 131072 + 65536);      // [16 ks][256 outs]

    const int tid = threadIdx.x;
    const int cg = blockIdx.x & 31;       // col group 0..31
    const int bg = blockIdx.x >> 5;       // batch group 0..3
    const int js = tid & 31;              // column lane 0..31
    const int ks = tid >> 5;              // k-slice 0..15 (warp id)
    const unsigned long long* hsu = (const unsigned long long*)hs;

    // staging mapping: thread half handles 4 batch pairs, 4 k's each
    const int half = tid >> 8;            // 0 or 1
    const int k4s = (tid & 255) << 2;     // 0..1020

    // epilogue mapping (threads 0..255)
    const int bp2 = tid >> 5;             // valid when tid<256: 0..7
    const int js2 = tid & 31;
    const int jo = (cg << 5) + js2;
    const int b0 = (bg << 4) + (bp2 << 1);

    // ---- one-time: stage Wh slice (1024 x 32) into smem ----
    {
        const float* wsrc = W + (size_t)DIN_ * DH_ + (cg << 5);
        for (int idx = tid; idx < (1024 * 32) / 4; idx += RNN_THREADS) {
            int r = idx >> 3;
            int c = (idx & 7) << 2;
            float4 v = *(const float4*)(wsrc + (size_t)r * DH_ + c);
            *(float4*)(ws + r * 32 + c) = v;
        }
    }
    __syncthreads();

    for (int t = 0; t < S_; ++t) {
        // ---- prefetch xp for this step (overlaps GEMV) ----
        float xp0 = 0.f, xp1 = 0.f;
        size_t i0 = 0, i1 = 0;
        if (tid < 256) {
            i0 = ((size_t)b0 * S_ + t) * DH_ + jo;
            i1 = i0 + (size_t)S_ * DH_;
            xp0 = out[i0];
            xp1 = out[i1];
        }

        // ---- stage h_prev (16 batches) into smem as batch-pairs ----
        {
            const float* base = (t == 0)
                ? (h0 + (size_t)(bg << 4) * DH_)
                : (g_hbuf[(t - 1) & 1] + (size_t)(bg << 4) * DH_);
#pragma unroll
            for (int q = 0; q < 4; ++q) {
                const int bp = (half << 2) + q;
                const float* r0 = base + (size_t)(bp << 1) * DH_ + k4s;
                float4 a = *(const float4*)r0;
                float4 b = *(const float4*)(r0 + DH_);
                float2* d = hs + bp * 1024 + k4s;
                d[0] = make_float2(a.x, b.x);
                d[1] = make_float2(a.y, b.y);
                d[2] = make_float2(a.z, b.z);
                d[3] = make_float2(a.w, b.w);
            }
        }
        __syncthreads();

        // ---- packed GEMV: warp = 64-k slice, lanes = 32 cols ----
        unsigned long long acc[8];
#pragma unroll
        for (int bp = 0; bp < 8; ++bp) acc[bp] = 0ull;

        const int kbase = ks << 6;           // 64 k per slice
        const float* wp = ws + kbase * 32 + js;
        const unsigned long long* hp = hsu + kbase;
#pragma unroll 4
        for (int kk = 0; kk < 64; kk += 2) {
            float w0 = wp[kk * 32];
            float w1 = wp[kk * 32 + 32];
            unsigned long long w20 = pack2(w0, w0);
            unsigned long long w21 = pack2(w1, w1);
#pragma unroll
            for (int bp = 0; bp < 8; ++bp) {
                ulonglong2 h2 = *(const ulonglong2*)(hp + bp * 1024 + kk);
                acc[bp] = ffma2(h2.x, w20, acc[bp]);
                acc[bp] = ffma2(h2.y, w21, acc[bp]);
            }
        }

        // ---- K-split reduction through smem: red[ks][bp*32+js] ----
#pragma unroll
        for (int bp = 0; bp < 8; ++bp)
            redu[(ks << 8) + (bp << 5) + js] = acc[bp];
        __syncthreads();

        if (tid < 256) {
            const unsigned long long* rp = redu + tid;
            float sx = 0.f, sy = 0.f;
#pragma unroll
            for (int q = 0; q < 16; ++q) {
                float x, y;
                unpack2(rp[q << 8], x, y);
                sx += x; sy += y;
            }
            float hv0 = tanhf(xp0 + sx);
            float hv1 = tanhf(xp1 + sy);
            out[i0] = hv0;
            out[i1] = hv1;
            float* hb = g_hbuf[t & 1];
            hb[(size_t)b0 * DH_ + jo] = hv0;
            hb[(size_t)(b0 + 1) * DH_ + jo] = hv1;
            if (t == S_ - 1) {
                hlast[(size_t)b0 * DH_ + jo] = hv0;
                hlast[(size_t)(b0 + 1) * DH_ + jo] = hv1;
            }
        }

        // ---- grid barrier: cumulative release/acquire, single thread ----
        __syncthreads();
        if (tid == 0) {
            unsigned long long addr = (unsigned long long)&g_bar;
            asm volatile("red.release.gpu.add.u32 [%0], 1;" :: "l"(addr) : "memory");
            const unsigned target = (unsigned)NCTA_RNN * (unsigned)(t + 1);
            unsigned v;
            do {
                asm volatile("ld.acquire.gpu.u32 %0, [%1];" : "=r"(v) : "l"(addr) : "memory");
            } while (v < target);
        }
        __syncthreads();
    }
}

// ---------------- launch ----------------
extern "C" void kernel_launch(void* const* d_in, const int* in_sizes, int n_in,
                              void* d_out, int out_size) {
    (void)in_sizes; (void)n_in; (void)out_size;
    const float* x  = (const float*)d_in[0];
    const float* h0 = (const float*)d_in[1];
    const float* W  = (const float*)d_in[2];
    const float* b  = (const float*)d_in[3];
    float* out = (float*)d_out;                       // (B,S,DH) outs
    float* hlast = out + (size_t)B_ * S_ * DH_;       // (B,DH) h_last

    cudaFuncSetAttribute(rnn_kernel, cudaFuncAttributeMaxDynamicSharedMemorySize, RNN_SMEM);

    dim3 g1(DH_ / 64, (B_ * S_) / 128);
    xproj_kernel<<<g1, 256>>>(x, W, b, out);
    reset_kernel<<<1, 1>>>();
    rnn_kernel<<<NCTA_RNN, RNN_THREADS, RNN_SMEM>>>(h0, W, out, hlast);
}

// round 6
// speedup vs baseline: 1.5932x; 1.0132x over previous
#include <cuda_runtime.h>

#define B_    64
#define S_    512
#define DIN_  512
#define DH_   1024
#define NCTA_RNN 128
#define RNN_THREADS 512
// smem: Wh slice (1024*32*4B=128KB) + h pairs (8*1024*8B=64KB) + reduction (16*256*8B=32KB)
#define RNN_SMEM (131072 + 65536 + 32768)

__device__ unsigned g_bars[4][32];                         // per-batch-group barrier, 128B apart
__device__ __align__(16) float2 g_hpair[2][32][DH_];       // ping-pong h, pre-interleaved batch pairs

// ---------------- packed f32x2 helpers (FFMA2 on sm_103a) ----------------
static __device__ __forceinline__ unsigned long long pack2(float x, float y) {
    unsigned long long r;
    asm("mov.b64 %0, {%1, %2};" : "=l"(r) : "f"(x), "f"(y));
    return r;
}
static __device__ __forceinline__ void unpack2(unsigned long long v, float &x, float &y) {
    asm("mov.b64 {%0, %1}, %2;" : "=f"(x), "=f"(y) : "l"(v));
}
static __device__ __forceinline__ unsigned long long ffma2(unsigned long long a,
                                                           unsigned long long b,
                                                           unsigned long long c) {
    unsigned long long d;
    asm("fma.rn.f32x2 %0, %1, %2, %3;" : "=l"(d) : "l"(a), "l"(b), "l"(c));
    return d;
}

static __device__ __forceinline__ float fast_tanh(float x) {
    // tanh(x) = 1 - 2/(exp(2x)+1); clamp avoids overflow. rel err ~1e-6.
    float xc = fminf(fmaxf(x, -15.f), 15.f);
    float e = __expf(2.f * xc);
    return 1.f - __fdividef(2.f, e + 1.f);
}

// ---------------- dummy kernels: shift ncu -s 5 window onto rnn_kernel ----------------
__global__ void nop_kernel() {}

// ---------------- Kernel 1: xproj = x @ Wx + b, written into outs region ----------------
__global__ __launch_bounds__(256) void xproj_kernel(
    const float* __restrict__ X,
    const float* __restrict__ W,      // full (1536,1024); Wx = rows [0,512)
    const float* __restrict__ bias,
    float* __restrict__ C)            // (32768, 1024) = outs region
{
    __shared__ __align__(16) float As[16][132];
    __shared__ __align__(16) float Bs[16][64];

    const int tid = threadIdx.x;
    const int m0 = blockIdx.y * 128;
    const int n0 = blockIdx.x * 64;
    const int tx = tid & 15;
    const int ty = tid >> 4;
    const int ar = tid >> 2;
    const int ac = (tid & 3) << 2;
    const int br = tid >> 4;
    const int bc = (tid & 15) << 2;

    unsigned long long acc[4][4];
#pragma unroll
    for (int i = 0; i < 4; ++i)
#pragma unroll
        for (int jj = 0; jj < 4; ++jj) acc[i][jj] = 0ull;

    for (int kt = 0; kt < DIN_; kt += 16) {
        float4 a0 = *(const float4*)(X + (size_t)(m0 + ar) * DIN_ + kt + ac);
        float4 a1 = *(const float4*)(X + (size_t)(m0 + ar + 64) * DIN_ + kt + ac);
        float4 bv = *(const float4*)(W + (size_t)(kt + br) * DH_ + n0 + bc);
        As[ac + 0][ar] = a0.x; As[ac + 1][ar] = a0.y;
        As[ac + 2][ar] = a0.z; As[ac + 3][ar] = a0.w;
        As[ac + 0][ar + 64] = a1.x; As[ac + 1][ar + 64] = a1.y;
        As[ac + 2][ar + 64] = a1.z; As[ac + 3][ar + 64] = a1.w;
        *(float4*)&Bs[br][bc] = bv;
        __syncthreads();

#pragma unroll
        for (int k = 0; k < 16; ++k) {
            const unsigned long long* ap =
                (const unsigned long long*)&As[k][ty << 3];
            ulonglong2 av0 = *(const ulonglong2*)(ap);
            ulonglong2 av1 = *(const ulonglong2*)(ap + 2);
            unsigned long long a2[4] = { av0.x, av0.y, av1.x, av1.y };
            float4 bq = *(const float4*)&Bs[k][tx << 2];
            unsigned long long b2[4] = { pack2(bq.x, bq.x), pack2(bq.y, bq.y),
                                         pack2(bq.z, bq.z), pack2(bq.w, bq.w) };
#pragma unroll
            for (int i = 0; i < 4; ++i)
#pragma unroll
                for (int jj = 0; jj < 4; ++jj)
                    acc[i][jj] = ffma2(a2[i], b2[jj], acc[i][jj]);
        }
        __syncthreads();
    }

    float4 bias4 = *(const float4*)(bias + n0 + (tx << 2));
#pragma unroll
    for (int i = 0; i < 4; ++i) {
        float l0, h0, l1, h1, l2, h2, l3, h3;
        unpack2(acc[i][0], l0, h0);
        unpack2(acc[i][1], l1, h1);
        unpack2(acc[i][2], l2, h2);
        unpack2(acc[i][3], l3, h3);
        int m = m0 + (ty << 3) + (i << 1);
        float4 v0 = make_float4(l0 + bias4.x, l1 + bias4.y, l2 + bias4.z, l3 + bias4.w);
        float4 v1 = make_float4(h0 + bias4.x, h1 + bias4.y, h2 + bias4.z, h3 + bias4.w);
        *(float4*)(C + (size_t)m * DH_ + n0 + (tx << 2)) = v0;
        *(float4*)(C + (size_t)(m + 1) * DH_ + n0 + (tx << 2)) = v1;
    }
}

// ---------------- barrier reset ----------------
__global__ void reset_kernel() {
    if (threadIdx.x < 4) g_bars[threadIdx.x][0] = 0u;
}

// ---------------- Kernel 2: persistent recurrence, 512 threads ----------------
__global__ __launch_bounds__(RNN_THREADS, 1) void rnn_kernel(
    const float* __restrict__ h0,
    const float* __restrict__ W,      // Wh = rows [512, 1536)
    float* __restrict__ out,          // (B,S,DH): xp in, h out (in place)
    float* __restrict__ hlast)        // (B, DH)
{
    extern __shared__ unsigned char sraw[];
    float*  ws   = (float*)sraw;                           // [1024][32] Wh slice
    float2* hs   = (float2*)(sraw + 131072);               // [8 pairs][1024]
    unsigned long long* redu =
        (unsigned long long*)(sraw + 131072 + 65536);      // [16 ks][256 outs]

    const int tid = threadIdx.x;
    const int cg = blockIdx.x & 31;       // col group 0..31
    const int bg = blockIdx.x >> 5;       // batch group 0..3
    const int js = tid & 31;
    const int ks = tid >> 5;              // warp id = k-slice 0..15
    const unsigned long long* hsu = (const unsigned long long*)hs;

    // t==0 staging mapping
    const int half = tid >> 8;
    const int k4s = (tid & 255) << 2;

    // epilogue mapping (threads 0..255)
    const int bp2 = tid >> 5;
    const int js2 = tid & 31;
    const int jo = (cg << 5) + js2;
    const int b0 = (bg << 4) + (bp2 << 1);

    volatile unsigned* bar = &g_bars[bg][0];

    // ---- one-time: stage Wh slice (1024 x 32) into smem ----
    {
        const float* wsrc = W + (size_t)DIN_ * DH_ + (cg << 5);
        for (int idx = tid; idx < (1024 * 32) / 4; idx += RNN_THREADS) {
            int r = idx >> 3;
            int c = (idx & 7) << 2;
            float4 v = *(const float4*)(wsrc + (size_t)r * DH_ + c);
            *(float4*)(ws + r * 32 + c) = v;
        }
    }

    // ---- prefetch xp for t=0 ----
    float xpc0 = 0.f, xpc1 = 0.f;
    size_t i0 = 0, i1 = 0;
    if (tid < 256) {
        i0 = ((size_t)b0 * S_) * DH_ + jo;
        i1 = i0 + (size_t)S_ * DH_;
        xpc0 = out[i0];
        xpc1 = out[i1];
    }
    __syncthreads();

    for (int t = 0; t < S_; ++t) {
        // ---- stage h_prev into smem ----
        if (t == 0) {
            const float* base = h0 + (size_t)(bg << 4) * DH_;
#pragma unroll
            for (int q = 0; q < 4; ++q) {
                const int bp = (half << 2) + q;
                const float* r0 = base + (size_t)(bp << 1) * DH_ + k4s;
                float4 a = *(const float4*)r0;
                float4 b = *(const float4*)(r0 + DH_);
                float2* d = hs + bp * 1024 + k4s;
                d[0] = make_float2(a.x, b.x);
                d[1] = make_float2(a.y, b.y);
                d[2] = make_float2(a.z, b.z);
                d[3] = make_float2(a.w, b.w);
            }
        } else {
            const ulonglong2* src = (const ulonglong2*)g_hpair[(t - 1) & 1][bg << 3];
            ulonglong2* dst = (ulonglong2*)hs;
#pragma unroll
            for (int q = 0; q < 8; ++q)
                dst[(q << 9) + tid] = src[(q << 9) + tid];
        }

        // ---- prefetch xp for t+1 (hidden under GEMV) ----
        float xpn0 = 0.f, xpn1 = 0.f;
        if (tid < 256 && t + 1 < S_) {
            xpn0 = out[i0 + DH_];
            xpn1 = out[i1 + DH_];
        }
        __syncthreads();

        // ---- packed GEMV: warp = 64-k slice, lanes = 32 cols ----
        unsigned long long acc[8];
#pragma unroll
        for (int bp = 0; bp < 8; ++bp) acc[bp] = 0ull;

        const int kbase = ks << 6;
        const float* wp = ws + kbase * 32 + js;
        const unsigned long long* hp = hsu + kbase;
#pragma unroll 4
        for (int kk = 0; kk < 64; kk += 2) {
            float w0 = wp[kk * 32];
            float w1 = wp[kk * 32 + 32];
            unsigned long long w20 = pack2(w0, w0);
            unsigned long long w21 = pack2(w1, w1);
#pragma unroll
            for (int bp = 0; bp < 8; ++bp) {
                ulonglong2 h2 = *(const ulonglong2*)(hp + bp * 1024 + kk);
                acc[bp] = ffma2(h2.x, w20, acc[bp]);
                acc[bp] = ffma2(h2.y, w21, acc[bp]);
            }
        }

        // ---- K-split reduction through smem ----
#pragma unroll
        for (int bp = 0; bp < 8; ++bp)
            redu[(ks << 8) + (bp << 5) + js] = acc[bp];
        __syncthreads();

        if (tid < 256) {
            const unsigned long long* rp = redu + tid;
            float sx = 0.f, sy = 0.f;
#pragma unroll
            for (int q = 0; q < 16; ++q) {
                float x, y;
                unpack2(rp[q << 8], x, y);
                sx += x; sy += y;
            }
            float hv0 = fast_tanh(xpc0 + sx);
            float hv1 = fast_tanh(xpc1 + sy);
            out[i0] = hv0;
            out[i1] = hv1;
            g_hpair[t & 1][(bg << 3) + bp2][jo] = make_float2(hv0, hv1);
            if (t == S_ - 1) {
                hlast[(size_t)b0 * DH_ + jo] = hv0;
                hlast[(size_t)(b0 + 1) * DH_ + jo] = hv1;
            }
            i0 += DH_;
            i1 += DH_;
        }
        xpc0 = xpn0;
        xpc1 = xpn1;

        // ---- per-bg barrier: arrive + wait (32 CTAs) ----
        __syncthreads();
        if (tid == 0) {
            unsigned long long addr = (unsigned long long)bar;
            asm volatile("red.release.gpu.add.u32 [%0], 1;" :: "l"(addr) : "memory");
            const unsigned target = 32u * (unsigned)(t + 1);
            unsigned v;
            do {
                asm volatile("ld.acquire.gpu.u32 %0, [%1];" : "=r"(v) : "l"(addr) : "memory");
            } while (v < target);
        }
        __syncthreads();
    }
}

// ---------------- launch ----------------
extern "C" void kernel_launch(void* const* d_in, const int* in_sizes, int n_in,
                              void* d_out, int out_size) {
    (void)in_sizes; (void)n_in; (void)out_size;
    const float* x  = (const float*)d_in[0];
    const float* h0 = (const float*)d_in[1];
    const float* W  = (const float*)d_in[2];
    const float* b  = (const float*)d_in[3];
    float* out = (float*)d_out;                       // (B,S,DH) outs
    float* hlast = out + (size_t)B_ * S_ * DH_;       // (B,DH) h_last

    cudaFuncSetAttribute(rnn_kernel, cudaFuncAttributeMaxDynamicSharedMemorySize, RNN_SMEM);

    // shift the ncu -s 5 -c 1 window so launch #5 is rnn_kernel
    nop_kernel<<<1, 32>>>();
    nop_kernel<<<1, 32>>>();
    nop_kernel<<<1, 32>>>();

    dim3 g1(DH_ / 64, (B_ * S_) / 128);
    xproj_kernel<<<g1, 256>>>(x, W, b, out);
    reset_kernel<<<1, 32>>>();
    rnn_kernel<<<NCTA_RNN, RNN_THREADS, RNN_SMEM>>>(h0, W, out, hlast);
}

// round 7
// speedup vs baseline: 1.6029x; 1.0060x over previous
#include <cuda_runtime.h>

#define B_    64
#define S_    512
#define DIN_  512
#define DH_   1024
#define NCTA_RNN 128
#define RNN_THREADS 512
// smem: Wh slice (1024*32*4B=128KB) + h pairs (8*1024*8B=64KB) + reduction (16*256*8B=32KB)
#define RNN_SMEM (131072 + 65536 + 32768)

__device__ unsigned g_bars[4][32];                         // per-batch-group barrier
__device__ __align__(16) float2 g_hpair[2][32][DH_];       // ping-pong h, pre-interleaved batch pairs

// ---------------- packed f32x2 helpers (FFMA2 on sm_103a) ----------------
static __device__ __forceinline__ unsigned long long pack2(float x, float y) {
    unsigned long long r;
    asm("mov.b64 %0, {%1, %2};" : "=l"(r) : "f"(x), "f"(y));
    return r;
}
static __device__ __forceinline__ void unpack2(unsigned long long v, float &x, float &y) {
    asm("mov.b64 {%0, %1}, %2;" : "=f"(x), "=f"(y) : "l"(v));
}
static __device__ __forceinline__ unsigned long long ffma2(unsigned long long a,
                                                           unsigned long long b,
                                                           unsigned long long c) {
    unsigned long long d;
    asm("fma.rn.f32x2 %0, %1, %2, %3;" : "=l"(d) : "l"(a), "l"(b), "l"(c));
    return d;
}

static __device__ __forceinline__ float fast_tanh(float x) {
    float xc = fminf(fmaxf(x, -15.f), 15.f);
    float e = __expf(2.f * xc);
    return 1.f - __fdividef(2.f, e + 1.f);
}

// ---------------- Kernel 1: xproj = x @ Wx + b, written into outs region ----------------
__global__ __launch_bounds__(256) void xproj_kernel(
    const float* __restrict__ X,
    const float* __restrict__ W,      // full (1536,1024); Wx = rows [0,512)
    const float* __restrict__ bias,
    float* __restrict__ C)            // (32768, 1024) = outs region
{
    __shared__ __align__(16) float As[16][132];
    __shared__ __align__(16) float Bs[16][64];

    const int tid = threadIdx.x;
    const int m0 = blockIdx.y * 128;
    const int n0 = blockIdx.x * 64;
    const int tx = tid & 15;
    const int ty = tid >> 4;
    const int ar = tid >> 2;
    const int ac = (tid & 3) << 2;
    const int br = tid >> 4;
    const int bc = (tid & 15) << 2;

    unsigned long long acc[4][4];
#pragma unroll
    for (int i = 0; i < 4; ++i)
#pragma unroll
        for (int jj = 0; jj < 4; ++jj) acc[i][jj] = 0ull;

    for (int kt = 0; kt < DIN_; kt += 16) {
        float4 a0 = *(const float4*)(X + (size_t)(m0 + ar) * DIN_ + kt + ac);
        float4 a1 = *(const float4*)(X + (size_t)(m0 + ar + 64) * DIN_ + kt + ac);
        float4 bv = *(const float4*)(W + (size_t)(kt + br) * DH_ + n0 + bc);
        As[ac + 0][ar] = a0.x; As[ac + 1][ar] = a0.y;
        As[ac + 2][ar] = a0.z; As[ac + 3][ar] = a0.w;
        As[ac + 0][ar + 64] = a1.x; As[ac + 1][ar + 64] = a1.y;
        As[ac + 2][ar + 64] = a1.z; As[ac + 3][ar + 64] = a1.w;
        *(float4*)&Bs[br][bc] = bv;
        __syncthreads();

#pragma unroll
        for (int k = 0; k < 16; ++k) {
            const unsigned long long* ap =
                (const unsigned long long*)&As[k][ty << 3];
            ulonglong2 av0 = *(const ulonglong2*)(ap);
            ulonglong2 av1 = *(const ulonglong2*)(ap + 2);
            unsigned long long a2[4] = { av0.x, av0.y, av1.x, av1.y };
            float4 bq = *(const float4*)&Bs[k][tx << 2];
            unsigned long long b2[4] = { pack2(bq.x, bq.x), pack2(bq.y, bq.y),
                                         pack2(bq.z, bq.z), pack2(bq.w, bq.w) };
#pragma unroll
            for (int i = 0; i < 4; ++i)
#pragma unroll
                for (int jj = 0; jj < 4; ++jj)
                    acc[i][jj] = ffma2(a2[i], b2[jj], acc[i][jj]);
        }
        __syncthreads();
    }

    float4 bias4 = *(const float4*)(bias + n0 + (tx << 2));
#pragma unroll
    for (int i = 0; i < 4; ++i) {
        float l0, h0, l1, h1, l2, h2, l3, h3;
        unpack2(acc[i][0], l0, h0);
        unpack2(acc[i][1], l1, h1);
        unpack2(acc[i][2], l2, h2);
        unpack2(acc[i][3], l3, h3);
        int m = m0 + (ty << 3) + (i << 1);
        float4 v0 = make_float4(l0 + bias4.x, l1 + bias4.y, l2 + bias4.z, l3 + bias4.w);
        float4 v1 = make_float4(h0 + bias4.x, h1 + bias4.y, h2 + bias4.z, h3 + bias4.w);
        *(float4*)(C + (size_t)m * DH_ + n0 + (tx << 2)) = v0;
        *(float4*)(C + (size_t)(m + 1) * DH_ + n0 + (tx << 2)) = v1;
    }
}

// ---------------- barrier reset ----------------
__global__ void reset_kernel() {
    if (threadIdx.x < 4) g_bars[threadIdx.x][0] = 0u;
}

// ---------------- Kernel 2: persistent recurrence, 512 threads ----------------
__global__ __launch_bounds__(RNN_THREADS, 1) void rnn_kernel(
    const float* __restrict__ h0,
    const float* __restrict__ W,      // Wh = rows [512, 1536)
    float* __restrict__ out,          // (B,S,DH): xp in, h out (in place)
    float* __restrict__ hlast)        // (B, DH)
{
    extern __shared__ unsigned char sraw[];
    float*  ws   = (float*)sraw;                           // [1024][32] Wh slice
    float2* hs   = (float2*)(sraw + 131072);               // [8 pairs][1024]
    unsigned long long* redu =
        (unsigned long long*)(sraw + 131072 + 65536);      // [16 ks][256 outs]

    const int tid = threadIdx.x;
    const int cg = blockIdx.x & 31;       // col group 0..31
    const int bg = blockIdx.x >> 5;       // batch group 0..3
    const int js = tid & 31;
    const int ks = tid >> 5;              // warp id = k-slice 0..15
    const unsigned long long* hsu = (const unsigned long long*)hs;

    // t==0 staging mapping
    const int half = tid >> 8;
    const int k4s = (tid & 255) << 2;

    // epilogue mapping (threads 0..255)
    const int bp2 = tid >> 5;
    const int js2 = tid & 31;
    const int jo = (cg << 5) + js2;
    const int b0 = (bg << 4) + (bp2 << 1);

    volatile unsigned* bar = &g_bars[bg][0];

    // ---- one-time: stage Wh slice (1024 x 32) into smem ----
    {
        const float* wsrc = W + (size_t)DIN_ * DH_ + (cg << 5);
        for (int idx = tid; idx < (1024 * 32) / 4; idx += RNN_THREADS) {
            int r = idx >> 3;
            int c = (idx & 7) << 2;
            float4 v = *(const float4*)(wsrc + (size_t)r * DH_ + c);
            *(float4*)(ws + r * 32 + c) = v;
        }
    }

    // ---- prefetch xp for t=0 ----
    float xpc0 = 0.f, xpc1 = 0.f;
    size_t i0 = 0, i1 = 0;
    if (tid < 256) {
        i0 = ((size_t)b0 * S_) * DH_ + jo;
        i1 = i0 + (size_t)S_ * DH_;
        xpc0 = out[i0];
        xpc1 = out[i1];
    }
    __syncthreads();

    for (int t = 0; t < S_; ++t) {
        // ---- stage h_prev into smem ----
        if (t == 0) {
            const float* base = h0 + (size_t)(bg << 4) * DH_;
#pragma unroll
            for (int q = 0; q < 4; ++q) {
                const int bp = (half << 2) + q;
                const float* r0 = base + (size_t)(bp << 1) * DH_ + k4s;
                float4 a = *(const float4*)r0;
                float4 b = *(const float4*)(r0 + DH_);
                float2* d = hs + bp * 1024 + k4s;
                d[0] = make_float2(a.x, b.x);
                d[1] = make_float2(a.y, b.y);
                d[2] = make_float2(a.z, b.z);
                d[3] = make_float2(a.w, b.w);
            }
        } else {
            const ulonglong2* src = (const ulonglong2*)g_hpair[(t - 1) & 1][bg << 3];
            ulonglong2* dst = (ulonglong2*)hs;
#pragma unroll
            for (int q = 0; q < 8; ++q)
                dst[(q << 9) + tid] = src[(q << 9) + tid];
        }

        // ---- prefetch xp for t+1 (hidden under GEMV) ----
        float xpn0 = 0.f, xpn1 = 0.f;
        if (tid < 256 && t + 1 < S_) {
            xpn0 = out[i0 + DH_];
            xpn1 = out[i1 + DH_];
        }
        __syncthreads();

        // ---- packed GEMV: warp = 64-k slice, lanes = 32 cols ----
        // h loads are LDS.64 broadcast (NOT LDS.128) to cut crossbar phases.
        unsigned long long acc[8];
#pragma unroll
        for (int bp = 0; bp < 8; ++bp) acc[bp] = 0ull;

        const int kbase = ks << 6;
        const float* wp = ws + kbase * 32 + js;
        const unsigned long long* hp = hsu + kbase;
#pragma unroll 4
        for (int kk = 0; kk < 64; kk += 2) {
            float w0 = wp[kk * 32];
            float w1 = wp[kk * 32 + 32];
            unsigned long long w20 = pack2(w0, w0);
            unsigned long long w21 = pack2(w1, w1);
#pragma unroll
            for (int bp = 0; bp < 8; ++bp) {
                unsigned long long h0v = hp[bp * 1024 + kk];        // LDS.64 bcast
                unsigned long long h1v = hp[bp * 1024 + kk + 1];    // LDS.64 bcast
                acc[bp] = ffma2(h0v, w20, acc[bp]);
                acc[bp] = ffma2(h1v, w21, acc[bp]);
            }
        }

        // ---- K-split reduction through smem ----
#pragma unroll
        for (int bp = 0; bp < 8; ++bp)
            redu[(ks << 8) + (bp << 5) + js] = acc[bp];
        __syncthreads();

        if (tid < 256) {
            const unsigned long long* rp = redu + tid;
            float sx = 0.f, sy = 0.f;
#pragma unroll
            for (int q = 0; q < 16; ++q) {
                float x, y;
                unpack2(rp[q << 8], x, y);
                sx += x; sy += y;
            }
            float hv0 = fast_tanh(xpc0 + sx);
            float hv1 = fast_tanh(xpc1 + sy);
            out[i0] = hv0;
            out[i1] = hv1;
            g_hpair[t & 1][(bg << 3) + bp2][jo] = make_float2(hv0, hv1);
            if (t == S_ - 1) {
                hlast[(size_t)b0 * DH_ + jo] = hv0;
                hlast[(size_t)(b0 + 1) * DH_ + jo] = hv1;
            }
            i0 += DH_;
            i1 += DH_;
        }
        xpc0 = xpn0;
        xpc1 = xpn1;

        // ---- per-bg barrier: arrive + wait (32 CTAs) ----
        __syncthreads();
        if (tid == 0) {
            unsigned long long addr = (unsigned long long)bar;
            asm volatile("red.release.gpu.add.u32 [%0], 1;" :: "l"(addr) : "memory");
            const unsigned target = 32u * (unsigned)(t + 1);
            unsigned v;
            do {
                asm volatile("ld.acquire.gpu.u32 %0, [%1];" : "=r"(v) : "l"(addr) : "memory");
            } while (v < target);
        }
        __syncthreads();
    }
}

// ---------------- launch ----------------
extern "C" void kernel_launch(void* const* d_in, const int* in_sizes, int n_in,
                              void* d_out, int out_size) {
    (void)in_sizes; (void)n_in; (void)out_size;
    const float* x  = (const float*)d_in[0];
    const float* h0 = (const float*)d_in[1];
    const float* W  = (const float*)d_in[2];
    const float* b  = (const float*)d_in[3];
    float* out = (float*)d_out;                       // (B,S,DH) outs
    float* hlast = out + (size_t)B_ * S_ * DH_;       // (B,DH) h_last

    cudaFuncSetAttribute(rnn_kernel, cudaFuncAttributeMaxDynamicSharedMemorySize, RNN_SMEM);

    dim3 g1(DH_ / 64, (B_ * S_) / 128);
    xproj_kernel<<<g1, 256>>>(x, W, b, out);
    reset_kernel<<<1, 32>>>();
    rnn_kernel<<<NCTA_RNN, RNN_THREADS, RNN_SMEM>>>(h0, W, out, hlast);
}